// round 14
// baseline (speedup 1.0000x reference)
#include <cuda_runtime.h>
#include <cuda_fp16.h>
#include <cstdint>

#define Hdim  1024
#define Bsz   64
#define Tlen  512
#define FOURH 4096
#define KEFF  2048            // all cells: [Wih (1024) | Whh (1024)], plain fp16
#define WSTRIDE 2176          // padded weight row stride (4352 B, breaks pow2 aliasing)
#define HSTR  1088            // padded activation/state row stride (2176 B)
#define NTILE 128
#define KC    128
#define NCTAS 128

#define CSZ  ((long)FOURH * WSTRIDE)
#define WTOT (4 * CSZ)                 // 71MB of halves (padded)

// ---------------- persistent scratch (device globals; no allocations) -------
__device__ __align__(16) __half g_W[(size_t)WTOT];
__device__ __align__(16) float  g_bias[4 * FOURH];
__device__ __align__(16) __half g_xh[(size_t)Tlen * Bsz * HSTR];  // [t][b][h], padded
__device__ __align__(16) __half g_hf0[3][Bsz * HSTR];             // 3-phase state buffers
__device__ __align__(16) __half g_hb0[3][Bsz * HSTR];
__device__ __align__(16) float  g_cb0[3][Bsz * HSTR];
__device__ __align__(16) __half g_hb1[3][Bsz * HSTR];
__device__ __align__(16) float  g_cb1[3][Bsz * HSTR];
__device__ unsigned g_done[4];         // per-cell progress: sum of completed iters over 32 CTAs

// ---------------- prep kernels ---------------------------------------------
// cell 0=f0, 1=b0, 2=f1, 3=b1; rows n' = 4*h + gate.
// K: [0,1024) Wih (feature-reversed for cell 1 only); [1024,2048) Whh; [2048,2176) pad.
__global__ void prep_weights(const float* __restrict__ Wih_f, const float* __restrict__ Whh_f,
                             const float* __restrict__ Wih_b, const float* __restrict__ Whh_b) {
    long idx = (long)blockIdx.x * 256 + threadIdx.x;
    if (idx >= WTOT) return;
    int  cell = (int)(idx / CSZ);
    long rem  = idx % CSZ;
    int  np   = (int)(rem / WSTRIDE);
    int  kk   = (int)(rem % WSTRIDE);
    if (kk >= KEFF) { g_W[idx] = __float2half_rn(0.f); return; }   // padding
    int  h = np >> 2, g = np & 3;
    int  n = g * Hdim + h;
    int  layer = cell >> 1;
    bool bwd   = cell & 1;
    const float* Wih = bwd ? Wih_b : Wih_f;
    const float* Whh = bwd ? Whh_b : Whh_f;

    float v;
    if (kk < Hdim) {
        int ksrc = (bwd && layer == 0) ? (Hdim - 1 - kk) : kk;  // feature reversal baked in
        v = Wih[((long)layer * FOURH + n) * Hdim + ksrc];
    } else {
        v = Whh[((long)layer * FOURH + n) * Hdim + (kk - Hdim)];
    }
    g_W[idx] = __float2half_rn(v);
}

// x: [B][T][H] fp32 -> g_xh [t][b*HSTR + h] fp16 (padding zeroed)
__global__ void prep_x(const float* __restrict__ x) {
    long idx = (long)blockIdx.x * 256 + threadIdx.x;
    if (idx >= (long)Tlen * Bsz * HSTR) return;
    int  h  = (int)(idx % HSTR);
    long bt = idx / HSTR;
    int  b  = (int)(bt % Bsz);
    int  t  = (int)(bt / Bsz);
    float v = (h < Hdim) ? x[((long)b * Tlen + t) * Hdim + h] : 0.f;
    g_xh[((long)t * Bsz + b) * HSTR + h] = __float2half_rn(v);
}

__global__ void prep_bias(const float* __restrict__ bih_f, const float* __restrict__ bhh_f,
                          const float* __restrict__ bih_b, const float* __restrict__ bhh_b) {
    int idx = blockIdx.x * 256 + threadIdx.x;
    if (idx >= 4 * FOURH) return;
    int cell = idx / FOURH, np = idx % FOURH;
    int h = np >> 2, g = np & 3;
    int n = g * Hdim + h;
    int layer = cell >> 1;
    bool bwd = cell & 1;
    const float* bi = bwd ? bih_b : bih_f;
    const float* bh = bwd ? bhh_b : bhh_f;
    g_bias[idx] = bi[layer * FOURH + n] + bh[layer * FOURH + n];
}

__global__ void prep_zero() {
    int idx = blockIdx.x * 256 + threadIdx.x;
    if (idx < 4) g_done[idx] = 0;                       // reset progress (graph replays!)
    if (idx >= Bsz * HSTR) return;
    __half z = __float2half_rn(0.f);
#pragma unroll
    for (int p = 0; p < 3; p++) {
        g_hf0[p][idx] = z; g_hb0[p][idx] = z; g_hb1[p][idx] = z;
        g_cb0[p][idx] = 0.f; g_cb1[p][idx] = 0.f;
    }
}

// ---------------- persistent step kernel ------------------------------------
// 128 CTAs co-resident; CTA = (cell = bid>>5, jt = bid&31).
// cells 0,1 iterate k=0..511 (t=k); cells 2,3 iterate k=1..512 (t=k-1).
// Flow sync via per-cell aggregate progress counters; 3-phase state buffers.
// Chunk order: independent K-half first; dependent-half gated mid-GEMM.
#define ROWH 136                              // halves per padded smem row
#define ROWB 272                              // bytes per padded smem row
#define A_OFF 0                               // activations: 64 rows
#define B_OFF (64 * ROWB)                     // W tile: 128 rows
#define STAGE_BYTES (192 * ROWB)              // 52224
#define NSTAGE 3
#define GATES_OFF (NSTAGE * STAGE_BYTES)      // 156672
#define SMEM_TOTAL (GATES_OFF + 64 * 128 * 4) // 189440

__device__ __forceinline__ void cp16(uint32_t dst, const void* src) {
    asm volatile("cp.async.cg.shared.global [%0], [%1], 16;\n" :: "r"(dst), "l"(src));
}
__device__ __forceinline__ void ldsm4(uint32_t& r0, uint32_t& r1, uint32_t& r2, uint32_t& r3,
                                      uint32_t addr) {
    asm volatile("ldmatrix.sync.aligned.m8n8.x4.shared.b16 {%0,%1,%2,%3}, [%4];"
                 : "=r"(r0), "=r"(r1), "=r"(r2), "=r"(r3) : "r"(addr));
}

// Block-wide wait until g_done[c] >= thr (no-op if thr <= 0).
__device__ __forceinline__ void wait_ge(int c, int thr) {
    if (thr > 0) {
        if (threadIdx.x == 0) {
            while ((int)(*(volatile unsigned*)&g_done[c]) < thr) { __nanosleep(64); }
            __threadfence();
        }
        __syncthreads();
    }
}

__global__ __launch_bounds__(256) void persist_kernel(float* __restrict__ out) {
    const int bid  = blockIdx.x;
    const int cell = bid >> 5;
    const int jt   = bid & 31;

    extern __shared__ __align__(1024) char smem[];
    float* gates = (float*)(smem + GATES_OFF);
    uint32_t smem_u32 = (uint32_t)__cvta_generic_to_shared(smem);

    const int tid  = threadIdx.x;
    const int warp = tid >> 5;
    const int lane = tid & 31;
    const int gid  = lane >> 2, tig = lane & 3;
    const int wM   = warp >> 2, wN = warp & 3;   // 2 x 4 warp grid over 64x128

    const int  nch = KEFF / KC;                  // 16
    const __half* Wg = g_W + (long)cell * CSZ + (long)jt * NTILE * WSTRIDE;
    const float*  bias = g_bias + cell * FOURH + jt * NTILE;

    // ldmatrix per-lane base offsets (byte offsets within a stage)
    const uint32_t a_lane_off = (uint32_t)((wM * 32 + (lane & 15)) * ROWB + (lane >> 4) * 16);
    const uint32_t b_lane_off = (uint32_t)(B_OFF +
        (wN * 32 + (lane >> 4) * 8 + (lane & 7)) * ROWB + ((lane >> 3) & 1) * 16);

    const int kbeg = (cell < 2) ? 0 : 1;
    const int kend = (cell < 2) ? (Tlen - 1) : Tlen;

    for (int k = kbeg; k <= kend; k++) {
        const int t   = (cell < 2) ? k : (k - 1);
        const int pp3 = t % 3;
        const int pm3 = (t + 2) % 3;             // (t-1) mod 3, safe at t=0

        // ---- start waits: self-pacing + WAR guards + early RAW deps (all trail
        //      steady state by >=1 iteration -> no stall in practice) ----
        if (cell == 0) {
            wait_ge(0, 32 * k);                  // self: siblings done k-1
            wait_ge(2, 32 * (k - 2));            // WAR: h_f0[t%3] readers done
        } else if (cell == 1) {
            wait_ge(0, 32 * (k - 1));            // WAR: h_b0/c_b0 readers (cell0)
            wait_ge(3, 32 * (k - 2));            // WAR: h_b0 reader (cell3)
        } else if (cell == 2) {
            wait_ge(2, 32 * (k - 1));            // self
            wait_ge(3, 32 * (k - 1));            // RAW: h_b1/c_b1(t-1)
        } else {
            wait_ge(3, 32 * (k - 1));            // self + RAW: h_b1/c_b1(t-1)
            wait_ge(2, 32 * (k - 2));            // WAR: h_b1/c_b1 readers
        }
        // mid-GEMM RAW gate (before dependent-half loads): producer + threshold
        const int mid_cell = (cell == 2) ? 0 : 1;
        const int mid_thr  = 32 * k;

        // A operand sources: two 1024-wide halves, all rows stride HSTR
        const __half *a0base, *a1base;
        if (cell < 2) {
            a0base = g_xh + (long)t * Bsz * HSTR;  // x_t (static -> independent half)
            a1base = g_hb0[pm3];                   // h_b0(t-1)  [dep: cell1 @ k-1]
        } else if (cell == 2) {
            a0base = g_hf0[pp3];                   // h_f0(t)    [dep: cell0 @ k-1]
            a1base = g_hb1[pm3];                   // h_b1(t-1)  [dep: cell3 @ k-1, early]
        } else {
            a0base = g_hb0[pp3];                   // h_b0(t)    [dep: cell1 @ k-1]
            a1base = g_hb1[pm3];                   // h_b1(t-1)  [early]
        }

        float acc[2][4][4];
#pragma unroll
        for (int i = 0; i < 2; i++)
#pragma unroll
            for (int j = 0; j < 4; j++)
#pragma unroll
                for (int q = 0; q < 4; q++) acc[i][j][q] = 0.f;

        // chunk order: independent/early half first, gated half second.
        // cells 0,1: c<8 -> x (kg=c*KC);        c>=8 -> h_b0 (kg unchanged mapping)
        // cells 2,3: c<8 -> h_b1 (kg=1024+cKC); c>=8 -> h_f0/h_b0 (kg=(c-8)*KC)
        auto chunk_kg = [&](int c) -> int {
            if (cell < 2) return c * KC;
            return (c < 8) ? (Hdim + c * KC) : ((c - 8) * KC);
        };

        auto load_chunk = [&](int c) {
            int s = c % NSTAGE;
            int kg = chunk_kg(c);
            const __half* ab; int koff;
            if (kg < Hdim) { ab = a0base; koff = kg; }
            else           { ab = a1base; koff = kg - Hdim; }
            uint32_t sbase = smem_u32 + (uint32_t)s * STAGE_BYTES;
#pragma unroll
            for (int it = 0; it < 4; it++) {                 // Act: 64 rows x 16 16B-chunks
                int idx = tid + it * 256;
                int r = idx >> 4, c8 = idx & 15;
                const void* src = ab + (long)r * HSTR + koff + c8 * 8;
                cp16(sbase + A_OFF + (uint32_t)(r * ROWB + c8 * 16), src);
            }
#pragma unroll
            for (int it = 0; it < 8; it++) {                 // W: 128 rows x 16 16B-chunks
                int idx = tid + it * 256;
                int r = idx >> 4, c8 = idx & 15;
                const void* src = Wg + (long)r * WSTRIDE + kg + c8 * 8;
                cp16(sbase + B_OFF + (uint32_t)(r * ROWB + c8 * 16), src);
            }
            asm volatile("cp.async.commit_group;\n");
        };

        auto compute_chunk = [&](int s) {
            uint32_t sbase = smem_u32 + (uint32_t)s * STAGE_BYTES;
            uint32_t abase = sbase + a_lane_off;
            uint32_t bbase = sbase + b_lane_off;
#pragma unroll
            for (int k16 = 0; k16 < KC / 16; k16++) {
                uint32_t ko = (uint32_t)k16 * 32;            // bytes
                uint32_t a[2][4], b[4][2];
#pragma unroll
                for (int i = 0; i < 2; i++)
                    ldsm4(a[i][0], a[i][1], a[i][2], a[i][3],
                          abase + (uint32_t)i * 16 * ROWB + ko);
#pragma unroll
                for (int jp = 0; jp < 2; jp++)
                    ldsm4(b[2 * jp][0], b[2 * jp][1], b[2 * jp + 1][0], b[2 * jp + 1][1],
                          bbase + (uint32_t)jp * 16 * ROWB + ko);
#pragma unroll
                for (int i = 0; i < 2; i++)
#pragma unroll
                    for (int j = 0; j < 4; j++) {
                        asm volatile(
                            "mma.sync.aligned.m16n8k16.row.col.f32.f16.f16.f32 "
                            "{%0,%1,%2,%3}, {%4,%5,%6,%7}, {%8,%9}, {%0,%1,%2,%3};\n"
                            : "+f"(acc[i][j][0]), "+f"(acc[i][j][1]),
                              "+f"(acc[i][j][2]), "+f"(acc[i][j][3])
                            : "r"(a[i][0]), "r"(a[i][1]), "r"(a[i][2]), "r"(a[i][3]),
                              "r"(b[j][0]), "r"(b[j][1]));
                    }
            }
        };

        // 3-stage pipeline; RAW gate fires before loading chunk 8 (at c=6).
        load_chunk(0);
        load_chunk(1);
        for (int c = 0; c < nch; c++) {
            asm volatile("cp.async.wait_group 1;\n");
            __syncthreads();
            compute_chunk(c % NSTAGE);
            if (c + 2 < nch) {
                if (c + 2 == 8) wait_ge(mid_cell, mid_thr);   // dependent-half gate
                load_chunk(c + 2);
            } else {
                asm volatile("cp.async.commit_group;\n");
            }
        }

        // epilogue: accum frags -> smem gates [64 batch][128 gate]
        __syncthreads();
#pragma unroll
        for (int i = 0; i < 2; i++)
#pragma unroll
            for (int j = 0; j < 4; j++) {
                int r0 = wM * 32 + i * 16 + gid;
                int cb = wN * 32 + j * 8 + 2 * tig;
                gates[r0 * 128 + cb]           = acc[i][j][0];
                gates[r0 * 128 + cb + 1]       = acc[i][j][1];
                gates[(r0 + 8) * 128 + cb]     = acc[i][j][2];
                gates[(r0 + 8) * 128 + cb + 1] = acc[i][j][3];
            }
        __syncthreads();

        const float* cprev = (cell < 2) ? g_cb0[pm3] : g_cb1[pm3];
        for (int p = tid; p < 2048; p += 256) {
            int b  = p >> 5, hl = p & 31;
            int hg = jt * 32 + hl;
            float4 gv = *(const float4*)(gates + b * 128 + 4 * hl);
            float4 bv = *(const float4*)(bias + 4 * hl);
            float ig = gv.x + bv.x;
            float fg = gv.y + bv.y;
            float gg = gv.z + bv.z;
            float og = gv.w + bv.w;
            float cp = cprev[b * HSTR + hg];
            float si = 1.f / (1.f + __expf(-ig));
            float sf = 1.f / (1.f + __expf(-fg));
            float so = 1.f / (1.f + __expf(-og));
            float cn = sf * cp + si * tanhf(gg);
            float hn = so * tanhf(cn);
            long sidx = (long)b * HSTR + hg;
            if (cell == 0) {                                  // f0: h feeds layer1
                g_hf0[pp3][sidx] = __float2half_rn(hn);
            } else if (cell == 1) {                           // b0: layer-0 carry
                g_hb0[pp3][sidx] = __float2half_rn(hn);
                g_cb0[pp3][sidx] = cn;
            } else {                                          // layer 1 -> outputs
                int halfoff = (cell == 2) ? 0 : Hdim;
                long oidx = ((long)b * Tlen + t) * (2 * Hdim) + halfoff + hg;
                out[oidx] = hn;
                out[(long)Bsz * Tlen * 2 * Hdim + oidx] = cn;
                if (t == Tlen - 1) {
                    long lbase = 2L * Bsz * Tlen * 2 * Hdim;
                    out[lbase + (long)b * 2 * Hdim + halfoff + hg] = hn;
                    out[lbase + (long)Bsz * 2 * Hdim + (long)b * 2 * Hdim + halfoff + hg] = cn;
                }
                if (cell == 3) {                              // b1: layer-1 carry
                    g_hb1[pp3][sidx] = __float2half_rn(hn);
                    g_cb1[pp3][sidx] = cn;
                }
            }
        }

        // ---- publish: all state writes visible, then bump progress ----
        __threadfence();
        __syncthreads();
        if (tid == 0) atomicAdd(&g_done[cell], 1u);
    }
}

// ---------------- launcher --------------------------------------------------
extern "C" void kernel_launch(void* const* d_in, const int* in_sizes, int n_in,
                              void* d_out, int out_size) {
    const float* x     = (const float*)d_in[0];
    const float* Wih_f = (const float*)d_in[1];
    const float* Whh_f = (const float*)d_in[2];
    const float* bih_f = (const float*)d_in[3];
    const float* bhh_f = (const float*)d_in[4];
    const float* Wih_b = (const float*)d_in[5];
    const float* Whh_b = (const float*)d_in[6];
    const float* bih_b = (const float*)d_in[7];
    const float* bhh_b = (const float*)d_in[8];
    float* out = (float*)d_out;

    cudaFuncSetAttribute(persist_kernel, cudaFuncAttributeMaxDynamicSharedMemorySize, SMEM_TOTAL);

    {
        long n = WTOT;
        prep_weights<<<(unsigned)((n + 255) / 256), 256>>>(Wih_f, Whh_f, Wih_b, Whh_b);
    }
    {
        long n = (long)Tlen * Bsz * HSTR;
        prep_x<<<(unsigned)((n + 255) / 256), 256>>>(x);
    }
    prep_bias<<<(4 * FOURH + 255) / 256, 256>>>(bih_f, bhh_f, bih_b, bhh_b);
    prep_zero<<<(Bsz * HSTR + 255) / 256, 256>>>();

    persist_kernel<<<NCTAS, 256, SMEM_TOTAL>>>(out);
}